// round 9
// baseline (speedup 1.0000x reference)
#include <cuda_runtime.h>
#include <math.h>
#include <float.h>

#define DDEPTH 7
#define IND   128
#define GRIDN 128
#define HIDN  256
#define BATCHN 2048
#define NT    129          // t in 0..128
#define TROW  512          // floats per (d,i) across all h: (P1,P2) per h

// k_main tiling
#define MAIN_TPB 512
#define BCB   512          // batches per CTA
#define IPC   16           // i's per CTA
#define NIC   8            // i-chunk count (128/IPC)
#define CHUNKF 128         // floats per t-row within one 64-h chunk

// ---------------- scratch (static device memory; no allocation) ----------------
__device__ float g_xmin[IND];
__device__ float g_xmax[IND];
__device__ float g_Zt[IND * BATCHN];             // z transposed: [i][b]
__device__ float g_sg[DDEPTH * IND * GRIDN];     // sorted grids
__device__ int   g_perm[DDEPTH * IND * GRIDN];   // permutation
// layout: [d][i][hc][t][128 floats]  (c_d folded in)
__device__ float g_T[(size_t)DDEPTH * IND * NT * TROW];
__device__ unsigned char g_tmap[(size_t)DDEPTH * IND * BATCHN];
__device__ float g_Hp[(size_t)NIC * BATCHN * HIDN];       // i-split partials
__device__ float g_Ha[BATCHN * HIDN];
__device__ float g_Hb[BATCHN * HIDN];
__device__ double g_sum[HIDN];
__device__ double g_sumsq[HIDN];
__device__ float2 g_bnp[HIDN];

// ---------------- 1. per-feature min/max over batch ----------------
__global__ void k_minmax(const float* __restrict__ x) {
    int i = blockIdx.x;
    float mn = FLT_MAX, mx = -FLT_MAX;
    for (int b = threadIdx.x; b < BATCHN; b += blockDim.x) {
        float v = x[b * IND + i];
        mn = fminf(mn, v);
        mx = fmaxf(mx, v);
    }
    __shared__ float smn[256], smx[256];
    smn[threadIdx.x] = mn; smx[threadIdx.x] = mx;
    __syncthreads();
    for (int s = 128; s > 0; s >>= 1) {
        if (threadIdx.x < s) {
            smn[threadIdx.x] = fminf(smn[threadIdx.x], smn[threadIdx.x + s]);
            smx[threadIdx.x] = fmaxf(smx[threadIdx.x], smx[threadIdx.x + s]);
        }
        __syncthreads();
    }
    if (threadIdx.x == 0) { g_xmin[i] = smn[0]; g_xmax[i] = smx[0]; }
}

// ---------------- 2. z transposed: g_Zt[i][b] ----------------
__global__ void k_z(const float* __restrict__ x) {
    int idx = blockIdx.x * blockDim.x + threadIdx.x;
    if (idx < BATCHN * IND) {
        int i = idx & (IND - 1);
        int b = idx >> 7;
        g_Zt[i * BATCHN + b] = (x[idx] - g_xmin[i]) / (g_xmax[i] - g_xmin[i] + 1e-6f);
    }
}

// ---------------- 3. sort grids per (d,i) via rank ----------------
__global__ void k_sort(const float* __restrict__ grids) {
    int di = blockIdx.x;
    int t  = threadIdx.x;
    __shared__ float sg[GRIDN];
    float g = grids[di * GRIDN + t];
    sg[t] = g;
    __syncthreads();
    int r = 0;
    #pragma unroll 8
    for (int j = 0; j < GRIDN; j++) {
        float gj = sg[j];
        r += (gj < g) || (gj == g && j < t);
    }
    g_sg[di * GRIDN + r]   = g;
    g_perm[di * GRIDN + r] = t;
}

// ---------------- 4. prefix tables with c_d folded; chunked layout ----------------
// 128 threads, each owns h pair (2*h2, 2*h2+1): float2 loads, float4 stores.
__global__ void __launch_bounds__(128) k_table(const float* __restrict__ fs,
                                               const float* __restrict__ ds) {
    __shared__ float ssg[GRIDN];
    __shared__ int   spm[GRIDN];
    int di = blockIdx.x;
    int d  = di >> 7;
    int h2 = threadIdx.x;               // 0..127
    ssg[h2] = g_sg[di * GRIDN + h2];
    spm[h2] = g_perm[di * GRIDN + h2];

    float w[DDEPTH], m = -FLT_MAX;
    for (int k = 0; k < DDEPTH; k++) m = fmaxf(m, ds[k]);
    float ssum = 0.f;
    for (int k = 0; k < DDEPTH; k++) { w[k] = expf(ds[k] - m); ssum += w[k]; }
    float cd = 0.f;
    for (int k = DDEPTH - 1; k >= d; --k) cd += w[k] / ssum;
    __syncthreads();

    const float* fbase = fs + (size_t)di * GRIDN * HIDN + 2 * h2;
    // chunk = h2>>5 ; float offset within 128-float row = (h2&31)*4
    float* base = g_T + (size_t)di * NT * TROW + (h2 >> 5) * (NT * CHUNKF) + (h2 & 31) * 4;
    float a10 = 0.f, a20 = 0.f, a11 = 0.f, a21 = 0.f;
    *(float4*)base = make_float4(0.f, 0.f, 0.f, 0.f);
    for (int t0 = 0; t0 < GRIDN; t0 += 4) {
        int p0 = spm[t0 + 0], p1 = spm[t0 + 1], p2 = spm[t0 + 2], p3 = spm[t0 + 3];
        float2 f0 = *(const float2*)(fbase + p0 * HIDN);
        float2 f1 = *(const float2*)(fbase + p1 * HIDN);
        float2 f2 = *(const float2*)(fbase + p2 * HIDN);
        float2 f3 = *(const float2*)(fbase + p3 * HIDN);
        float g0 = ssg[t0 + 0], g1 = ssg[t0 + 1], g2 = ssg[t0 + 2], g3 = ssg[t0 + 3];
        a10 += f0.x; a20 = fmaf(g0, f0.x, a20);
        a11 += f0.y; a21 = fmaf(g0, f0.y, a21);
        *(float4*)(base + (size_t)(t0 + 1) * CHUNKF) = make_float4(cd*a10, cd*a20, cd*a11, cd*a21);
        a10 += f1.x; a20 = fmaf(g1, f1.x, a20);
        a11 += f1.y; a21 = fmaf(g1, f1.y, a21);
        *(float4*)(base + (size_t)(t0 + 2) * CHUNKF) = make_float4(cd*a10, cd*a20, cd*a11, cd*a21);
        a10 += f2.x; a20 = fmaf(g2, f2.x, a20);
        a11 += f2.y; a21 = fmaf(g2, f2.y, a21);
        *(float4*)(base + (size_t)(t0 + 3) * CHUNKF) = make_float4(cd*a10, cd*a20, cd*a11, cd*a21);
        a10 += f3.x; a20 = fmaf(g3, f3.x, a20);
        a11 += f3.y; a21 = fmaf(g3, f3.y, a21);
        *(float4*)(base + (size_t)(t0 + 4) * CHUNKF) = make_float4(cd*a10, cd*a20, cd*a11, cd*a21);
    }
}

// ---------------- 5. t[d,i,b] = #{ g < z } ----------------
__global__ void k_tmap() {
    int di = blockIdx.x;
    __shared__ float sg[GRIDN];
    if (threadIdx.x < GRIDN) sg[threadIdx.x] = g_sg[di * GRIDN + threadIdx.x];
    __syncthreads();
    int i = di & (IND - 1);
    for (int b = threadIdx.x; b < BATCHN; b += blockDim.x) {
        float z = g_Zt[i * BATCHN + b];
        int t = 0;
        #pragma unroll
        for (int s = 64; s > 0; s >>= 1) {
            int nt = t + s;
            if (nt <= GRIDN && sg[nt - 1] < z) t = nt;
        }
        g_tmap[(size_t)di * BATCHN + b] = (unsigned char)t;
    }
}

// ---------------- 6. main kernel: direct LDG gathers (L1-resident slices) ----------------
// grid = 128: bc = x&3 (512 b), hc = (x>>2)&3 (64 h), ic = x>>4 (16 i).
// 512 threads: hx = tid&31 (h-pair in chunk), bg = tid>>5 (32 b's each).
// Per (d,i) step each warp's gather = 32 consecutive float4 of row t -> coalesced
// LDG.128; slice (66 KB) stays L1-resident across the 512-b sweep. No staging,
// no barriers except one per il to bound warp drift.
__global__ void __launch_bounds__(MAIN_TPB, 1) k_main() {
    __shared__ float z_s[IPC * BCB];    // 32 KB

    int bc = blockIdx.x & 3;
    int hc = (blockIdx.x >> 2) & 3;
    int ic = blockIdx.x >> 4;
    int tid = threadIdx.x;
    int hx = tid & 31;
    int bg = tid >> 5;
    int b0 = bc * BCB;
    int i0 = ic * IPC;

    for (int idx = tid; idx < IPC * BCB; idx += MAIN_TPB) {
        int il = idx >> 9, bl = idx & (BCB - 1);
        z_s[idx] = g_Zt[(i0 + il) * BATCHN + b0 + bl];
    }
    __syncthreads();

    float2 acc[32];
    #pragma unroll
    for (int j = 0; j < 32; j++) acc[j] = make_float2(0.f, 0.f);

    for (int il = 0; il < IPC; il++) {
        const float* zb = z_s + il * BCB + bg * 32;
        #pragma unroll 1
        for (int d = 0; d < DDEPTH; d++) {
            const float4* rb = (const float4*)
                (g_T + (size_t)(d * IND + i0 + il) * (NT * TROW) + (size_t)hc * (NT * CHUNKF));
            const unsigned int* tbw = (const unsigned int*)
                (g_tmap + (size_t)(d * IND + i0 + il) * BATCHN + b0 + bg * 32);
            #pragma unroll
            for (int q = 0; q < 8; q++) {
                unsigned int tw = tbw[q];
                float4 z4 = *(const float4*)(zb + q * 4);
                float4 v0 = rb[(tw & 255u) * 32 + hx];
                float4 v1 = rb[((tw >> 8) & 255u) * 32 + hx];
                float4 v2 = rb[((tw >> 16) & 255u) * 32 + hx];
                float4 v3 = rb[(tw >> 24) * 32 + hx];
                acc[q*4+0].x = fmaf(z4.x, v0.x, acc[q*4+0].x - v0.y);
                acc[q*4+0].y = fmaf(z4.x, v0.z, acc[q*4+0].y - v0.w);
                acc[q*4+1].x = fmaf(z4.y, v1.x, acc[q*4+1].x - v1.y);
                acc[q*4+1].y = fmaf(z4.y, v1.z, acc[q*4+1].y - v1.w);
                acc[q*4+2].x = fmaf(z4.z, v2.x, acc[q*4+2].x - v2.y);
                acc[q*4+2].y = fmaf(z4.z, v2.z, acc[q*4+2].y - v2.w);
                acc[q*4+3].x = fmaf(z4.w, v3.x, acc[q*4+3].x - v3.y);
                acc[q*4+3].y = fmaf(z4.w, v3.z, acc[q*4+3].y - v3.w);
            }
        }
        __syncthreads();   // bound warp drift: keep L1 working set ~1-2 slices
    }

    int h0 = (hc * 32 + hx) * 2;
    float* outp = g_Hp + (size_t)ic * BATCHN * HIDN;
    #pragma unroll
    for (int j = 0; j < 32; j++) {
        int b = b0 + bg * 32 + j;
        *(float2*)&outp[(size_t)b * HIDN + h0] = acc[j];
    }
}

// ---------------- 7. MLP head ----------------
__global__ void k_zstat() {
    int t = threadIdx.x;
    g_sum[t] = 0.0; g_sumsq[t] = 0.0;
}

__device__ __forceinline__ float gelu_exact(float y) {
    return 0.5f * y * (1.0f + erff(y * 0.70710678118654752440f));
}

// act==0: src = g_Hp, sum NIC partials. act==1: BN(prev params)+GELU on src.
__global__ void __launch_bounds__(256) k_gemm(const float* __restrict__ W,
                                              const float* __restrict__ bias,
                                              const float* __restrict__ src,
                                              float* __restrict__ dst,
                                              int act) {
    __shared__ float Hs[16 * HIDN];
    int b0 = blockIdx.x * 16;
    int tid = threadIdx.x;
    for (int idx = tid; idx < 16 * HIDN; idx += 256) {
        size_t off = (size_t)b0 * HIDN + idx;
        float v;
        if (act) {
            v = src[off];
            float2 p = g_bnp[idx & (HIDN - 1)];
            v = gelu_exact(fmaf(v, p.x, p.y));
        } else {
            v = 0.f;
            #pragma unroll
            for (int p = 0; p < NIC; p++)
                v += src[(size_t)p * BATCHN * HIDN + off];
        }
        Hs[idx] = v;
    }
    __syncthreads();

    float acc[16];
    #pragma unroll
    for (int b = 0; b < 16; b++) acc[b] = 0.f;
    int hxc = tid;
    for (int k4 = 0; k4 < HIDN / 4; k4++) {
        float w0 = W[(4 * k4 + 0) * HIDN + hxc];
        float w1 = W[(4 * k4 + 1) * HIDN + hxc];
        float w2 = W[(4 * k4 + 2) * HIDN + hxc];
        float w3 = W[(4 * k4 + 3) * HIDN + hxc];
        #pragma unroll
        for (int b = 0; b < 16; b++) {
            float4 hv = *(const float4*)&Hs[b * HIDN + 4 * k4];
            acc[b] = fmaf(hv.x, w0, fmaf(hv.y, w1, fmaf(hv.z, w2, fmaf(hv.w, w3, acc[b]))));
        }
    }
    float bsv = bias[hxc];
    double s1 = 0.0, s2 = 0.0;
    #pragma unroll
    for (int b = 0; b < 16; b++) {
        float y = acc[b] + bsv;
        dst[(size_t)(b0 + b) * HIDN + hxc] = y;
        s1 += (double)y;
        s2 += (double)y * (double)y;
    }
    atomicAdd(&g_sum[hxc], s1);
    atomicAdd(&g_sumsq[hxc], s2);
}

__global__ void k_bnfin(const float* __restrict__ gamma, const float* __restrict__ beta) {
    int h = threadIdx.x;
    double mean = g_sum[h] / (double)BATCHN;
    double var  = g_sumsq[h] / (double)BATCHN - mean * mean;
    float scale = gamma[h] * rsqrtf((float)var + 1e-5f);
    float shift = beta[h] - (float)mean * scale;
    g_bnp[h] = make_float2(scale, shift);
    g_sum[h] = 0.0; g_sumsq[h] = 0.0;
}

__global__ void k_final(const float* __restrict__ Wout, const float* __restrict__ bout,
                        float* __restrict__ out) {
    int b = blockIdx.x * 8 + (threadIdx.x >> 5);
    int lane = threadIdx.x & 31;
    const float* hr = g_Hb + (size_t)b * HIDN;
    float s = 0.f;
    #pragma unroll
    for (int k = lane; k < HIDN; k += 32) {
        float2 p = g_bnp[k];
        float y = gelu_exact(fmaf(hr[k], p.x, p.y));
        s = fmaf(y, Wout[k], s);
    }
    #pragma unroll
    for (int o = 16; o > 0; o >>= 1) s += __shfl_down_sync(0xffffffffu, s, o);
    if (lane == 0) out[b] = s + bout[0];
}

// ---------------- launch ----------------
extern "C" void kernel_launch(void* const* d_in, const int* in_sizes, int n_in,
                              void* d_out, int out_size) {
    const float* x     = (const float*)d_in[0];
    const float* grids = (const float*)d_in[1];
    const float* fs    = (const float*)d_in[2];
    const float* ds    = (const float*)d_in[3];
    const float* mlpW  = (const float*)d_in[4];
    const float* mlpb  = (const float*)d_in[5];
    const float* gamma = (const float*)d_in[6];
    const float* beta  = (const float*)d_in[7];
    const float* Wout  = (const float*)d_in[8];
    const float* bout  = (const float*)d_in[9];
    float* out = (float*)d_out;

    float* Ha; float* Hb; float* Hp;
    cudaGetSymbolAddress((void**)&Ha, g_Ha);
    cudaGetSymbolAddress((void**)&Hb, g_Hb);
    cudaGetSymbolAddress((void**)&Hp, g_Hp);

    k_minmax<<<IND, 256>>>(x);
    k_z<<<(BATCHN * IND + 255) / 256, 256>>>(x);
    k_sort<<<DDEPTH * IND, GRIDN>>>(grids);
    k_table<<<DDEPTH * IND, 128>>>(fs, ds);
    k_tmap<<<DDEPTH * IND, 256>>>();
    k_main<<<128, MAIN_TPB>>>();

    k_zstat<<<1, HIDN>>>();
    k_gemm<<<BATCHN / 16, 256>>>(mlpW + 0 * HIDN * HIDN, mlpb + 0 * HIDN, Hp, Hb, 0);
    k_bnfin<<<1, HIDN>>>(gamma + 0 * HIDN, beta + 0 * HIDN);
    k_gemm<<<BATCHN / 16, 256>>>(mlpW + 1 * HIDN * HIDN, mlpb + 1 * HIDN, Hb, Ha, 1);
    k_bnfin<<<1, HIDN>>>(gamma + 1 * HIDN, beta + 1 * HIDN);
    k_gemm<<<BATCHN / 16, 256>>>(mlpW + 2 * HIDN * HIDN, mlpb + 2 * HIDN, Ha, Hb, 1);
    k_bnfin<<<1, HIDN>>>(gamma + 2 * HIDN, beta + 2 * HIDN);
    k_final<<<BATCHN / 8, 256>>>(Wout, bout, out);
}